// round 13
// baseline (speedup 1.0000x reference)
#include <cuda_runtime.h>
#include <math.h>

#define NN 100000
#define NE 1600000
#define C  128
#define OC 64
#define NG 64

// ---------------- static device scratch (zero-initialized .bss) --------------
__device__ float g_bufA[(size_t)NN * C];   // z (agg out) / h2 (gemm2 in-place)
__device__ float g_bufB[(size_t)NN * C];   // saved copy of x during the launch
__device__ int   g_col[NE];
__device__ int   g_cnt[NN];                // zeroed inline by k_scan each replay
__device__ int   g_rowptr[NN + 1];
__device__ int   g_fillptr[NN];
__device__ float g_dinv[NN];
__device__ int   g_gcnt[NG];               // zeroed inline by k_scan each replay
__device__ int   g_goff[NG + 1];

__device__ __forceinline__ int detect64(const int* e32) {
    int is64 = 1;
    #pragma unroll
    for (int i = 0; i < 8; i++) if (e32[2 * i + 1] != 0) is64 = 0;
    return is64;
}

// idx 0: in-degree histogram + per-graph node histogram
__global__ void k_hist_all(const void* ei, const void* bat, int E, int N) {
    int tid = blockIdx.x * blockDim.x + threadIdx.x;
    int stride = gridDim.x * blockDim.x;
    int is64 = detect64((const int*)ei);
    if (is64) {
        const long long* e = (const long long*)ei;
        for (int i = tid; i < E; i += stride)
            atomicAdd(&g_cnt[(int)e[(size_t)E + i]], 1);
        const long long* b = (const long long*)bat;
        for (int i = tid; i < N; i += stride) atomicAdd(&g_gcnt[(int)b[i]], 1);
    } else {
        const int* e = (const int*)ei;
        for (int i = tid; i < E; i += stride)
            atomicAdd(&g_cnt[e[E + i]], 1);
        const int* b = (const int*)bat;
        for (int i = tid; i < N; i += stride) atomicAdd(&g_gcnt[b[i]], 1);
    }
}

// idx 1: single-block fused scan: rowptr/fillptr, dinv, zero cnt, rowptr[N]=E,
// goff from gcnt, zero gcnt.
__global__ void k_scan(int n) {
    __shared__ int wsum[32];
    __shared__ int carry_s;
    int tid = threadIdx.x;
    int lane = tid & 31, wid = tid >> 5;
    if (tid == 0) carry_s = 0;
    __syncthreads();

    for (int base = 0; base < n; base += 1024) {
        int i = base + tid;
        int v = (i < n) ? g_cnt[i] : 0;
        int x = v;
        #pragma unroll
        for (int o = 1; o < 32; o <<= 1) {
            int t = __shfl_up_sync(~0u, x, o);
            if (lane >= o) x += t;
        }
        if (lane == 31) wsum[wid] = x;
        __syncthreads();
        if (wid == 0) {
            int s = wsum[lane];
            #pragma unroll
            for (int o = 1; o < 32; o <<= 1) {
                int t = __shfl_up_sync(~0u, s, o);
                if (lane >= o) s += t;
            }
            wsum[lane] = s;
        }
        __syncthreads();
        int carry = carry_s;
        int warpoff = (wid > 0) ? wsum[wid - 1] : 0;
        int excl = carry + warpoff + x - v;
        if (i < n) {
            g_rowptr[i] = excl;
            g_fillptr[i] = excl;
            g_dinv[i] = rsqrtf((float)(v + 1));
            g_cnt[i] = 0;
        }
        __syncthreads();
        if (tid == 1023) carry_s = carry + wsum[31];
        __syncthreads();
    }
    if (tid == 0) {
        g_rowptr[n] = carry_s;
        int s = 0;
        #pragma unroll
        for (int g = 0; g < NG; g++) {
            g_goff[g] = s;
            s += g_gcnt[g];
            g_gcnt[g] = 0;
        }
        g_goff[NG] = s;
    }
}

// idx 2: CSR column fill (measured 27us)
__global__ void k_fill(const void* ei, int E) {
    int tid = blockIdx.x * blockDim.x + threadIdx.x;
    int stride = gridDim.x * blockDim.x;
    int is64 = detect64((const int*)ei);
    if (is64) {
        const long long* e = (const long long*)ei;
        for (int i = tid; i < E; i += stride) {
            int d = (int)e[(size_t)E + i];
            int s = (int)e[i];
            g_col[atomicAdd(&g_fillptr[d], 1)] = s;
        }
    } else {
        const int* e = (const int*)ei;
        for (int i = tid; i < E; i += stride) {
            int d = e[E + i];
            int s = e[i];
            g_col[atomicAdd(&g_fillptr[d], 1)] = s;
        }
    }
}

// idx 3 (PROFILED): layer-1 aggregation, weighted gather, x-backup.
// 2 nodes per warp (16-lane sub-warps), 2 channel groups (64 ch each) across
// the grid => 2 independent edge chains per warp, halved per-chain latency.
// z_i = di*(di*u_i + sum_j dj*u_j); saves self rows to bufB (both ch groups
// together cover all 128 channels of every node).
__global__ __launch_bounds__(256) void k_agg1(
    const float* __restrict__ Uin, float* __restrict__ Zout,
    float* __restrict__ save, int n)
{
    int gwarp = (blockIdx.x * blockDim.x + threadIdx.x) >> 5;
    int lane = threadIdx.x & 31;
    int half = lane >> 4;            // node slot (0..1)
    int sl   = lane & 15;            // lane within sub-warp

    int wpg = (n + 1) >> 1;          // warp-pairs per channel group
    int cg = gwarp / wpg;            // channel group (0..1)
    if (cg >= 2) return;
    int node = (gwarp - cg * wpg) * 2 + half;
    if (node >= n) return;

    int poff = cg * 16;              // float4 offset of this 64-ch group
    const float4* U4 = (const float4*)Uin;
    size_t base = (size_t)node * 32 + poff + sl;

    float di = g_dinv[node];
    float4 s4 = U4[base];
    ((float4*)save)[base] = s4;
    float4 acc = make_float4(s4.x * di, s4.y * di, s4.z * di, s4.w * di);

    int e = g_rowptr[node];
    int end = g_rowptr[node + 1];

    for (; e + 8 <= end; e += 8) {
        int s[8];
        #pragma unroll
        for (int j = 0; j < 8; j++) s[j] = g_col[e + j];
        float w[8];
        #pragma unroll
        for (int j = 0; j < 8; j++) w[j] = g_dinv[s[j]];
        float4 v[8];
        #pragma unroll
        for (int j = 0; j < 8; j++) v[j] = U4[(size_t)s[j] * 32 + poff + sl];
        #pragma unroll
        for (int j = 0; j < 8; j++) {
            acc.x = fmaf(w[j], v[j].x, acc.x);
            acc.y = fmaf(w[j], v[j].y, acc.y);
            acc.z = fmaf(w[j], v[j].z, acc.z);
            acc.w = fmaf(w[j], v[j].w, acc.w);
        }
    }
    for (; e < end; e++) {
        int s = g_col[e];
        float w = g_dinv[s];
        float4 v = U4[(size_t)s * 32 + poff + sl];
        acc.x = fmaf(w, v.x, acc.x);
        acc.y = fmaf(w, v.y, acc.y);
        acc.z = fmaf(w, v.z, acc.z);
        acc.w = fmaf(w, v.w, acc.w);
    }

    ((float4*)Zout)[base] =
        make_float4(di * acc.x, di * acc.y, di * acc.z, di * acc.w);
}

// idx 5: layer-2 aggregation, PURE SUM (Y pre-scaled by dinv in gemm1
// epilogue), same 2-node/2-group layout, 8-wide unroll.
__global__ __launch_bounds__(256) void k_agg2(
    const float* __restrict__ Yin, float* __restrict__ Zout, int n)
{
    int gwarp = (blockIdx.x * blockDim.x + threadIdx.x) >> 5;
    int lane = threadIdx.x & 31;
    int half = lane >> 4;
    int sl   = lane & 15;

    int wpg = (n + 1) >> 1;
    int cg = gwarp / wpg;
    if (cg >= 2) return;
    int node = (gwarp - cg * wpg) * 2 + half;
    if (node >= n) return;

    int poff = cg * 16;
    const float4* Y4 = (const float4*)Yin;
    size_t base = (size_t)node * 32 + poff + sl;

    float4 acc = Y4[base];           // self (already scaled)

    int e = g_rowptr[node];
    int end = g_rowptr[node + 1];

    for (; e + 8 <= end; e += 8) {
        int s[8];
        #pragma unroll
        for (int j = 0; j < 8; j++) s[j] = g_col[e + j];
        float4 v[8];
        #pragma unroll
        for (int j = 0; j < 8; j++) v[j] = Y4[(size_t)s[j] * 32 + poff + sl];
        #pragma unroll
        for (int j = 0; j < 8; j++) {
            acc.x += v[j].x; acc.y += v[j].y;
            acc.z += v[j].z; acc.w += v[j].w;
        }
    }
    for (; e < end; e++) {
        float4 v = Y4[(size_t)g_col[e] * 32 + poff + sl];
        acc.x += v.x; acc.y += v.y; acc.z += v.z; acc.w += v.w;
    }

    float di = g_dinv[node];
    ((float4*)Zout)[base] =
        make_float4(di * acc.x, di * acc.y, di * acc.z, di * acc.w);
}

// GEMM body: out = relu(Z @ W + b), optionally post-scaled by dinv.
// 64-row tile, full W in smem, k-paired inner loop. In-place safe.
__device__ __forceinline__ void gemm_body(
    const float* __restrict__ Z, const float* __restrict__ W,
    const float* __restrict__ bias, float* __restrict__ H, int n, int blk,
    bool scale_out)
{
    __shared__ float Ws[C * C];
    __shared__ float Zs[64 * C];
    int tid = threadIdx.x;
    int row0 = blk * 64;

    for (int i = tid; i < C * C; i += 256) Ws[i] = W[i];
    for (int i = tid; i < 64 * C; i += 256) {
        int r = row0 + (i >> 7);
        Zs[i] = (r < n) ? Z[(size_t)r * C + (i & 127)] : 0.0f;
    }
    __syncthreads();

    int tn = tid & 31;
    int tm = tid >> 5;
    float acc[8][4];
    #pragma unroll
    for (int r = 0; r < 8; r++)
        #pragma unroll
        for (int c = 0; c < 4; c++) acc[r][c] = 0.0f;

    #pragma unroll 8
    for (int k2 = 0; k2 < C / 2; k2++) {
        float4 wv0 = *(const float4*)&Ws[(2 * k2) * C + tn * 4];
        float4 wv1 = *(const float4*)&Ws[(2 * k2 + 1) * C + tn * 4];
        #pragma unroll
        for (int r = 0; r < 8; r++) {
            float2 z = *(const float2*)&Zs[(tm * 8 + r) * C + 2 * k2];
            acc[r][0] += z.x * wv0.x + z.y * wv1.x;
            acc[r][1] += z.x * wv0.y + z.y * wv1.y;
            acc[r][2] += z.x * wv0.z + z.y * wv1.z;
            acc[r][3] += z.x * wv0.w + z.y * wv1.w;
        }
    }

    float4 bv = ((const float4*)bias)[tn];
    #pragma unroll
    for (int r = 0; r < 8; r++) {
        int row = row0 + tm * 8 + r;
        if (row < n) {
            float s = scale_out ? g_dinv[row] : 1.0f;
            float4 o;
            o.x = s * fmaxf(acc[r][0] + bv.x, 0.f);
            o.y = s * fmaxf(acc[r][1] + bv.y, 0.f);
            o.z = s * fmaxf(acc[r][2] + bv.z, 0.f);
            o.w = s * fmaxf(acc[r][3] + bv.w, 0.f);
            *(float4*)&H[(size_t)row * C + tn * 4] = o;
        }
    }
}

// idx 4: gemm1 -> writes dinv.*relu(z@W1+b1) into xbuf (pre-scaled for agg2)
__global__ __launch_bounds__(256, 2) void k_gemm_scaled(
    const float* __restrict__ Z, const float* __restrict__ W,
    const float* __restrict__ bias, float* __restrict__ H, int n)
{
    gemm_body(Z, W, bias, H, n, blockIdx.x, true);
}

// idx 6: gemm2 (plain relu) fused with restore (blocks >= gb copy bufB -> xbuf)
__global__ __launch_bounds__(256, 2) void k_gemm_rest(
    const float* __restrict__ Z, const float* __restrict__ W,
    const float* __restrict__ bias, float* __restrict__ H, int n, int gb,
    float* __restrict__ xdst, const float* __restrict__ xsrc, int n4, int rb)
{
    if (blockIdx.x >= gb) {
        int tid = (blockIdx.x - gb) * 256 + threadIdx.x;
        int stride = rb * 256;
        const float4* s4 = (const float4*)xsrc;
        float4* d4 = (float4*)xdst;
        for (int i = tid; i < n4; i += stride) d4[i] = s4[i];
        return;
    }
    gemm_body(Z, W, bias, H, n, blockIdx.x, false);
}

// idx 7: fused mean-pool + linear head, one block per graph
__global__ __launch_bounds__(256) void k_poolhead(
    const float* __restrict__ H, const float* __restrict__ Wl,
    const float* __restrict__ bl, float* __restrict__ out)
{
    __shared__ float4 sh[8][32];
    __shared__ float pooled[C];
    int g = blockIdx.x;
    int rr = threadIdx.x >> 5;
    int c4 = threadIdx.x & 31;
    int s = g_goff[g], e = g_goff[g + 1];
    const float4* H4 = (const float4*)H;
    float4 acc = make_float4(0.f, 0.f, 0.f, 0.f);
    for (int r = s + rr; r < e; r += 8) {
        float4 v = H4[(size_t)r * 32 + c4];
        acc.x += v.x; acc.y += v.y; acc.z += v.z; acc.w += v.w;
    }
    sh[rr][c4] = acc;
    __syncthreads();
    if (rr == 0) {
        #pragma unroll
        for (int j = 1; j < 8; j++) {
            float4 v = sh[j][c4];
            acc.x += v.x; acc.y += v.y; acc.z += v.z; acc.w += v.w;
        }
        float inv = 1.0f / fmaxf((float)(e - s), 1.0f);
        pooled[c4 * 4 + 0] = acc.x * inv;
        pooled[c4 * 4 + 1] = acc.y * inv;
        pooled[c4 * 4 + 2] = acc.z * inv;
        pooled[c4 * 4 + 3] = acc.w * inv;
    }
    __syncthreads();
    if (threadIdx.x < OC) {
        int o = threadIdx.x;
        float a = bl[o];
        #pragma unroll 4
        for (int k = 0; k < C; k++) a += pooled[k] * Wl[k * OC + o];
        out[g * OC + o] = a;
    }
}

// ---------------- launch (8 nodes) -------------------------------------------
extern "C" void kernel_launch(void* const* d_in, const int* in_sizes, int n_in,
                              void* d_out, int out_size) {
    float*       xbuf = (float*)d_in[0];          // harness buffer; restored each call
    const void*  ei   = d_in[1];
    const void*  bat  = d_in[2];
    const float* W1   = (const float*)d_in[3];
    const float* b1   = (const float*)d_in[4];
    const float* W2   = (const float*)d_in[5];
    const float* b2   = (const float*)d_in[6];
    const float* Wl   = (const float*)d_in[7];
    const float* bl   = (const float*)d_in[8];
    float* out = (float*)d_out;

    int N = in_sizes[0] / C;
    int E = in_sizes[1] / 2;
    int gb = (N + 63) / 64;
    int wpg = (N + 1) / 2;                       // warp-pairs per channel group
    int ab = (wpg * 2 * 32 + 255) / 256;         // agg blocks (2 ch groups)
    int rb = 512;

    k_hist_all   <<<1024, 256>>>(ei, bat, E, N);                     // 0
    k_scan       <<<1, 1024>>>(N);                                   // 1
    k_fill       <<<1024, 256>>>(ei, E);                             // 2
    // layer 1: weighted gather from xbuf (2-node split), save x -> bufB
    k_agg1       <<<ab, 256>>>(xbuf, g_bufA, g_bufB, N);             // 3  <-- profiled
    // gemm1 writes dinv.*h1 into xbuf (pre-scaled for agg2)
    k_gemm_scaled<<<gb, 256>>>(g_bufA, W1, b1, xbuf, N);             // 4
    // layer 2: pure-sum gather from xbuf (2-node split)
    k_agg2       <<<ab, 256>>>(xbuf, g_bufA, N);                     // 5
    // gemm2 in-place on bufA + restore x from bufB
    k_gemm_rest  <<<gb + rb, 256>>>(g_bufA, W2, b2, g_bufA, N, gb,
                                    xbuf, g_bufB, N * 32, rb);       // 6
    k_poolhead   <<<NG, 256>>>(g_bufA, Wl, bl, out);                 // 7
}

// round 14
// speedup vs baseline: 1.0490x; 1.0490x over previous
#include <cuda_runtime.h>
#include <math.h>

#define NN 100000
#define NE 1600000
#define C  128
#define OC 64
#define NG 64

// ---------------- static device scratch (zero-initialized .bss) --------------
__device__ float g_bufA[(size_t)NN * C];   // z (agg out) / h2 (gemm2 in-place)
__device__ float g_bufB[(size_t)NN * C];   // saved copy of x during the launch
__device__ int   g_col[NE];
__device__ int   g_cnt[NN];                // zeroed inline by k_scan each replay
__device__ int   g_rowptr[NN + 1];
__device__ int   g_fillptr[NN];
__device__ float g_dinv[NN];
__device__ int   g_gcnt[NG];               // zeroed inline by k_scan each replay
__device__ int   g_goff[NG + 1];

__device__ __forceinline__ int detect64(const int* e32) {
    int is64 = 1;
    #pragma unroll
    for (int i = 0; i < 8; i++) if (e32[2 * i + 1] != 0) is64 = 0;
    return is64;
}

// idx 0: in-degree histogram + per-graph node histogram
__global__ void k_hist_all(const void* ei, const void* bat, int E, int N) {
    int tid = blockIdx.x * blockDim.x + threadIdx.x;
    int stride = gridDim.x * blockDim.x;
    int is64 = detect64((const int*)ei);
    if (is64) {
        const long long* e = (const long long*)ei;
        for (int i = tid; i < E; i += stride)
            atomicAdd(&g_cnt[(int)e[(size_t)E + i]], 1);
        const long long* b = (const long long*)bat;
        for (int i = tid; i < N; i += stride) atomicAdd(&g_gcnt[(int)b[i]], 1);
    } else {
        const int* e = (const int*)ei;
        for (int i = tid; i < E; i += stride)
            atomicAdd(&g_cnt[e[E + i]], 1);
        const int* b = (const int*)bat;
        for (int i = tid; i < N; i += stride) atomicAdd(&g_gcnt[b[i]], 1);
    }
}

// idx 1: single-block fused scan: rowptr/fillptr, dinv, zero cnt, rowptr[N]=E,
// goff from gcnt, zero gcnt.
__global__ void k_scan(int n) {
    __shared__ int wsum[32];
    __shared__ int carry_s;
    int tid = threadIdx.x;
    int lane = tid & 31, wid = tid >> 5;
    if (tid == 0) carry_s = 0;
    __syncthreads();

    for (int base = 0; base < n; base += 1024) {
        int i = base + tid;
        int v = (i < n) ? g_cnt[i] : 0;
        int x = v;
        #pragma unroll
        for (int o = 1; o < 32; o <<= 1) {
            int t = __shfl_up_sync(~0u, x, o);
            if (lane >= o) x += t;
        }
        if (lane == 31) wsum[wid] = x;
        __syncthreads();
        if (wid == 0) {
            int s = wsum[lane];
            #pragma unroll
            for (int o = 1; o < 32; o <<= 1) {
                int t = __shfl_up_sync(~0u, s, o);
                if (lane >= o) s += t;
            }
            wsum[lane] = s;
        }
        __syncthreads();
        int carry = carry_s;
        int warpoff = (wid > 0) ? wsum[wid - 1] : 0;
        int excl = carry + warpoff + x - v;
        if (i < n) {
            g_rowptr[i] = excl;
            g_fillptr[i] = excl;
            g_dinv[i] = rsqrtf((float)(v + 1));
            g_cnt[i] = 0;
        }
        __syncthreads();
        if (tid == 1023) carry_s = carry + wsum[31];
        __syncthreads();
    }
    if (tid == 0) {
        g_rowptr[n] = carry_s;
        int s = 0;
        #pragma unroll
        for (int g = 0; g < NG; g++) {
            g_goff[g] = s;
            s += g_gcnt[g];
            g_gcnt[g] = 0;
        }
        g_goff[NG] = s;
    }
}

// idx 2: CSR column fill (measured 27us)
__global__ void k_fill(const void* ei, int E) {
    int tid = blockIdx.x * blockDim.x + threadIdx.x;
    int stride = gridDim.x * blockDim.x;
    int is64 = detect64((const int*)ei);
    if (is64) {
        const long long* e = (const long long*)ei;
        for (int i = tid; i < E; i += stride) {
            int d = (int)e[(size_t)E + i];
            int s = (int)e[i];
            g_col[atomicAdd(&g_fillptr[d], 1)] = s;
        }
    } else {
        const int* e = (const int*)ei;
        for (int i = tid; i < E; i += stride) {
            int d = e[E + i];
            int s = e[i];
            g_col[atomicAdd(&g_fillptr[d], 1)] = s;
        }
    }
}

// idx 3 (PROFILED): layer-1 aggregation (R9-proven exact form).
// z_i = di*(di*u_i + sum_j dj*u_j); saves self rows (backup of x) to bufB.
// warp per node, lane owns 4 channels, 8-wide edge unroll.
__global__ __launch_bounds__(256) void k_agg1(
    const float* __restrict__ Uin, float* __restrict__ Zout,
    float* __restrict__ save, int n)
{
    int node = (blockIdx.x * blockDim.x + threadIdx.x) >> 5;
    int lane = threadIdx.x & 31;
    if (node >= n) return;

    const float4* U4 = (const float4*)Uin;
    float di = g_dinv[node];
    float4 s4 = U4[(size_t)node * 32 + lane];
    ((float4*)save)[(size_t)node * 32 + lane] = s4;
    float4 acc = make_float4(s4.x * di, s4.y * di, s4.z * di, s4.w * di);

    int e = g_rowptr[node];
    int end = g_rowptr[node + 1];

    for (; e + 8 <= end; e += 8) {
        int s[8];
        #pragma unroll
        for (int j = 0; j < 8; j++) s[j] = g_col[e + j];
        float w[8];
        #pragma unroll
        for (int j = 0; j < 8; j++) w[j] = g_dinv[s[j]];
        float4 v[8];
        #pragma unroll
        for (int j = 0; j < 8; j++) v[j] = U4[(size_t)s[j] * 32 + lane];
        #pragma unroll
        for (int j = 0; j < 8; j++) {
            acc.x = fmaf(w[j], v[j].x, acc.x);
            acc.y = fmaf(w[j], v[j].y, acc.y);
            acc.z = fmaf(w[j], v[j].z, acc.z);
            acc.w = fmaf(w[j], v[j].w, acc.w);
        }
    }
    for (; e < end; e++) {
        int s = g_col[e];
        float w = g_dinv[s];
        float4 v = U4[(size_t)s * 32 + lane];
        acc.x = fmaf(w, v.x, acc.x);
        acc.y = fmaf(w, v.y, acc.y);
        acc.z = fmaf(w, v.z, acc.z);
        acc.w = fmaf(w, v.w, acc.w);
    }

    ((float4*)Zout)[(size_t)node * 32 + lane] =
        make_float4(di * acc.x, di * acc.y, di * acc.z, di * acc.w);
}

// idx 5: layer-2 aggregation, PURE SUM (Y pre-scaled by dinv in gemm1
// epilogue). warp per node, 8-wide unroll — same shape as agg1, minus the
// per-edge dinv gather chain and per-edge FMAs.
__global__ __launch_bounds__(256) void k_agg2(
    const float* __restrict__ Yin, float* __restrict__ Zout, int n)
{
    int node = (blockIdx.x * blockDim.x + threadIdx.x) >> 5;
    int lane = threadIdx.x & 31;
    if (node >= n) return;

    const float4* Y4 = (const float4*)Yin;
    float4 acc = Y4[(size_t)node * 32 + lane];        // self (already scaled)

    int e = g_rowptr[node];
    int end = g_rowptr[node + 1];

    for (; e + 8 <= end; e += 8) {
        int s[8];
        #pragma unroll
        for (int j = 0; j < 8; j++) s[j] = g_col[e + j];
        float4 v[8];
        #pragma unroll
        for (int j = 0; j < 8; j++) v[j] = Y4[(size_t)s[j] * 32 + lane];
        #pragma unroll
        for (int j = 0; j < 8; j++) {
            acc.x += v[j].x; acc.y += v[j].y;
            acc.z += v[j].z; acc.w += v[j].w;
        }
    }
    for (; e < end; e++) {
        float4 v = Y4[(size_t)g_col[e] * 32 + lane];
        acc.x += v.x; acc.y += v.y; acc.z += v.z; acc.w += v.w;
    }

    float di = g_dinv[node];
    ((float4*)Zout)[(size_t)node * 32 + lane] =
        make_float4(di * acc.x, di * acc.y, di * acc.z, di * acc.w);
}

// GEMM body: out = relu(Z @ W + b), optionally post-scaled by dinv.
// 64-row tile, full W in smem, k-paired inner loop. In-place safe.
__device__ __forceinline__ void gemm_body(
    const float* __restrict__ Z, const float* __restrict__ W,
    const float* __restrict__ bias, float* __restrict__ H, int n, int blk,
    bool scale_out)
{
    __shared__ float Ws[C * C];
    __shared__ float Zs[64 * C];
    int tid = threadIdx.x;
    int row0 = blk * 64;

    for (int i = tid; i < C * C; i += 256) Ws[i] = W[i];
    for (int i = tid; i < 64 * C; i += 256) {
        int r = row0 + (i >> 7);
        Zs[i] = (r < n) ? Z[(size_t)r * C + (i & 127)] : 0.0f;
    }
    __syncthreads();

    int tn = tid & 31;
    int tm = tid >> 5;
    float acc[8][4];
    #pragma unroll
    for (int r = 0; r < 8; r++)
        #pragma unroll
        for (int c = 0; c < 4; c++) acc[r][c] = 0.0f;

    #pragma unroll 8
    for (int k2 = 0; k2 < C / 2; k2++) {
        float4 wv0 = *(const float4*)&Ws[(2 * k2) * C + tn * 4];
        float4 wv1 = *(const float4*)&Ws[(2 * k2 + 1) * C + tn * 4];
        #pragma unroll
        for (int r = 0; r < 8; r++) {
            float2 z = *(const float2*)&Zs[(tm * 8 + r) * C + 2 * k2];
            acc[r][0] += z.x * wv0.x + z.y * wv1.x;
            acc[r][1] += z.x * wv0.y + z.y * wv1.y;
            acc[r][2] += z.x * wv0.z + z.y * wv1.z;
            acc[r][3] += z.x * wv0.w + z.y * wv1.w;
        }
    }

    float4 bv = ((const float4*)bias)[tn];
    #pragma unroll
    for (int r = 0; r < 8; r++) {
        int row = row0 + tm * 8 + r;
        if (row < n) {
            float s = scale_out ? g_dinv[row] : 1.0f;
            float4 o;
            o.x = s * fmaxf(acc[r][0] + bv.x, 0.f);
            o.y = s * fmaxf(acc[r][1] + bv.y, 0.f);
            o.z = s * fmaxf(acc[r][2] + bv.z, 0.f);
            o.w = s * fmaxf(acc[r][3] + bv.w, 0.f);
            *(float4*)&H[(size_t)row * C + tn * 4] = o;
        }
    }
}

// idx 4: gemm1 -> writes dinv.*relu(z@W1+b1) into xbuf (pre-scaled for agg2)
__global__ __launch_bounds__(256, 2) void k_gemm_scaled(
    const float* __restrict__ Z, const float* __restrict__ W,
    const float* __restrict__ bias, float* __restrict__ H, int n)
{
    gemm_body(Z, W, bias, H, n, blockIdx.x, true);
}

// idx 6: gemm2 (plain relu) fused with restore (blocks >= gb copy bufB -> xbuf)
__global__ __launch_bounds__(256, 2) void k_gemm_rest(
    const float* __restrict__ Z, const float* __restrict__ W,
    const float* __restrict__ bias, float* __restrict__ H, int n, int gb,
    float* __restrict__ xdst, const float* __restrict__ xsrc, int n4, int rb)
{
    if (blockIdx.x >= gb) {
        int tid = (blockIdx.x - gb) * 256 + threadIdx.x;
        int stride = rb * 256;
        const float4* s4 = (const float4*)xsrc;
        float4* d4 = (float4*)xdst;
        for (int i = tid; i < n4; i += stride) d4[i] = s4[i];
        return;
    }
    gemm_body(Z, W, bias, H, n, blockIdx.x, false);
}

// idx 7: fused mean-pool + linear head, one block per graph
__global__ __launch_bounds__(256) void k_poolhead(
    const float* __restrict__ H, const float* __restrict__ Wl,
    const float* __restrict__ bl, float* __restrict__ out)
{
    __shared__ float4 sh[8][32];
    __shared__ float pooled[C];
    int g = blockIdx.x;
    int rr = threadIdx.x >> 5;
    int c4 = threadIdx.x & 31;
    int s = g_goff[g], e = g_goff[g + 1];
    const float4* H4 = (const float4*)H;
    float4 acc = make_float4(0.f, 0.f, 0.f, 0.f);
    for (int r = s + rr; r < e; r += 8) {
        float4 v = H4[(size_t)r * 32 + c4];
        acc.x += v.x; acc.y += v.y; acc.z += v.z; acc.w += v.w;
    }
    sh[rr][c4] = acc;
    __syncthreads();
    if (rr == 0) {
        #pragma unroll
        for (int j = 1; j < 8; j++) {
            float4 v = sh[j][c4];
            acc.x += v.x; acc.y += v.y; acc.z += v.z; acc.w += v.w;
        }
        float inv = 1.0f / fmaxf((float)(e - s), 1.0f);
        pooled[c4 * 4 + 0] = acc.x * inv;
        pooled[c4 * 4 + 1] = acc.y * inv;
        pooled[c4 * 4 + 2] = acc.z * inv;
        pooled[c4 * 4 + 3] = acc.w * inv;
    }
    __syncthreads();
    if (threadIdx.x < OC) {
        int o = threadIdx.x;
        float a = bl[o];
        #pragma unroll 4
        for (int k = 0; k < C; k++) a += pooled[k] * Wl[k * OC + o];
        out[g * OC + o] = a;
    }
}

// ---------------- launch (8 nodes) -------------------------------------------
extern "C" void kernel_launch(void* const* d_in, const int* in_sizes, int n_in,
                              void* d_out, int out_size) {
    float*       xbuf = (float*)d_in[0];          // harness buffer; restored each call
    const void*  ei   = d_in[1];
    const void*  bat  = d_in[2];
    const float* W1   = (const float*)d_in[3];
    const float* b1   = (const float*)d_in[4];
    const float* W2   = (const float*)d_in[5];
    const float* b2   = (const float*)d_in[6];
    const float* Wl   = (const float*)d_in[7];
    const float* bl   = (const float*)d_in[8];
    float* out = (float*)d_out;

    int N = in_sizes[0] / C;
    int E = in_sizes[1] / 2;
    int gb = (N + 63) / 64;
    int ab = (N * 32 + 255) / 256;
    int rb = 512;

    k_hist_all   <<<1024, 256>>>(ei, bat, E, N);                     // 0
    k_scan       <<<1, 1024>>>(N);                                   // 1
    k_fill       <<<1024, 256>>>(ei, E);                             // 2
    // layer 1: weighted gather from xbuf, save x -> bufB (R9-proven)
    k_agg1       <<<ab, 256>>>(xbuf, g_bufA, g_bufB, N);             // 3  <-- profiled
    // gemm1 writes dinv.*h1 into xbuf (pre-scaled for agg2)
    k_gemm_scaled<<<gb, 256>>>(g_bufA, W1, b1, xbuf, N);             // 4
    // layer 2: pure-sum gather from xbuf (8-unroll, warp-per-node)
    k_agg2       <<<ab, 256>>>(xbuf, g_bufA, N);                     // 5
    // gemm2 in-place on bufA + restore x from bufB
    k_gemm_rest  <<<gb + rb, 256>>>(g_bufA, W2, b2, g_bufA, N, gb,
                                    xbuf, g_bufB, N * 32, rb);       // 6
    k_poolhead   <<<NG, 256>>>(g_bufA, Wl, bl, out);                 // 7
}

// round 15
// speedup vs baseline: 1.0988x; 1.0474x over previous
#include <cuda_runtime.h>
#include <math.h>

#define NN 100000
#define NE 1600000
#define C  128
#define OC 64
#define NG 64
#define NB 64      // degree bins
#define FB 1024    // fill blocks
#define SB 64      // scatter (perm) blocks appended to fill

// ---------------- static device scratch (zero-initialized .bss) --------------
__device__ float g_bufA[(size_t)NN * C];   // z (agg out) / h2 (gemm2 in-place)
__device__ float g_bufB[(size_t)NN * C];   // saved copy of x during the launch
__device__ int   g_col[NE];
__device__ int   g_cnt[NN];                // zeroed inline by k_scan each replay
__device__ int   g_rowptr[NN + 1];
__device__ int   g_fillptr[NN];
__device__ float g_dinv[NN];
__device__ int   g_gcnt[NG];               // zeroed inline by k_scan each replay
__device__ int   g_goff[NG + 1];
__device__ int   g_dbin[NB];               // degree histogram (zeroed in k_scan)
__device__ int   g_dbinp[NB];              // bin cursors (re-based each call)
__device__ int   g_perm[NN];               // degree-sorted node order

__device__ __forceinline__ int detect64(const int* e32) {
    int is64 = 1;
    #pragma unroll
    for (int i = 0; i < 8; i++) if (e32[2 * i + 1] != 0) is64 = 0;
    return is64;
}

// idx 0: in-degree histogram + per-graph node histogram
__global__ void k_hist_all(const void* ei, const void* bat, int E, int N) {
    int tid = blockIdx.x * blockDim.x + threadIdx.x;
    int stride = gridDim.x * blockDim.x;
    int is64 = detect64((const int*)ei);
    if (is64) {
        const long long* e = (const long long*)ei;
        for (int i = tid; i < E; i += stride)
            atomicAdd(&g_cnt[(int)e[(size_t)E + i]], 1);
        const long long* b = (const long long*)bat;
        for (int i = tid; i < N; i += stride) atomicAdd(&g_gcnt[(int)b[i]], 1);
    } else {
        const int* e = (const int*)ei;
        for (int i = tid; i < E; i += stride)
            atomicAdd(&g_cnt[e[E + i]], 1);
        const int* b = (const int*)bat;
        for (int i = tid; i < N; i += stride) atomicAdd(&g_gcnt[b[i]], 1);
    }
}

// idx 1: single-block fused scan: rowptr/fillptr, dinv, degree-bin histogram,
// zero cnt, rowptr[N]=E, goff from gcnt, bin bases, zero bins/gcnt.
__global__ void k_scan(int n) {
    __shared__ int wsum[32];
    __shared__ int carry_s;
    int tid = threadIdx.x;
    int lane = tid & 31, wid = tid >> 5;
    if (tid == 0) carry_s = 0;
    __syncthreads();

    for (int base = 0; base < n; base += 1024) {
        int i = base + tid;
        int v = (i < n) ? g_cnt[i] : 0;
        if (i < n) atomicAdd(&g_dbin[v < NB - 1 ? v : NB - 1], 1);
        int x = v;
        #pragma unroll
        for (int o = 1; o < 32; o <<= 1) {
            int t = __shfl_up_sync(~0u, x, o);
            if (lane >= o) x += t;
        }
        if (lane == 31) wsum[wid] = x;
        __syncthreads();
        if (wid == 0) {
            int s = wsum[lane];
            #pragma unroll
            for (int o = 1; o < 32; o <<= 1) {
                int t = __shfl_up_sync(~0u, s, o);
                if (lane >= o) s += t;
            }
            wsum[lane] = s;
        }
        __syncthreads();
        int carry = carry_s;
        int warpoff = (wid > 0) ? wsum[wid - 1] : 0;
        int excl = carry + warpoff + x - v;
        if (i < n) {
            g_rowptr[i] = excl;
            g_fillptr[i] = excl;
            g_dinv[i] = rsqrtf((float)(v + 1));
            g_cnt[i] = 0;
        }
        __syncthreads();
        if (tid == 1023) carry_s = carry + wsum[31];
        __syncthreads();
    }
    if (tid == 0) {
        g_rowptr[n] = carry_s;
        int s = 0;
        #pragma unroll
        for (int g = 0; g < NG; g++) {
            g_goff[g] = s;
            s += g_gcnt[g];
            g_gcnt[g] = 0;
        }
        g_goff[NG] = s;
        // degree-bin exclusive bases -> cursors; zero histogram for next call
        int bs = 0;
        #pragma unroll
        for (int b = 0; b < NB; b++) {
            int t = g_dbin[b];
            g_dbinp[b] = bs;
            bs += t;
            g_dbin[b] = 0;
        }
    }
}

// idx 2: CSR column fill + (extra blocks) degree-sorted permutation scatter.
__global__ void k_fill(const void* ei, int E, int N) {
    if (blockIdx.x >= FB) {
        // scatter nodes into degree-sorted order (deg from rowptr diffs)
        int tid = (blockIdx.x - FB) * 256 + threadIdx.x;
        int stride = SB * 256;
        for (int i = tid; i < N; i += stride) {
            int deg = g_rowptr[i + 1] - g_rowptr[i];
            int b = deg < NB - 1 ? deg : NB - 1;
            int p = atomicAdd(&g_dbinp[b], 1);
            g_perm[p] = i;
        }
        return;
    }
    int tid = blockIdx.x * blockDim.x + threadIdx.x;
    int stride = FB * blockDim.x;
    int is64 = detect64((const int*)ei);
    if (is64) {
        const long long* e = (const long long*)ei;
        for (int i = tid; i < E; i += stride) {
            int d = (int)e[(size_t)E + i];
            int s = (int)e[i];
            g_col[atomicAdd(&g_fillptr[d], 1)] = s;
        }
    } else {
        const int* e = (const int*)ei;
        for (int i = tid; i < E; i += stride) {
            int d = e[E + i];
            int s = e[i];
            g_col[atomicAdd(&g_fillptr[d], 1)] = s;
        }
    }
}

// idx 3 (PROFILED) / idx 5: z_i = di*(di*u_i + sum_j dj*u_j)  (R9-proven form)
// warp per node, lane owns 4 channels, 8-wide edge unroll.
// Node order = degree-sorted perm => uniform trip counts within each block.
__global__ __launch_bounds__(256) void k_agg(
    const float* __restrict__ Uin, float* __restrict__ Zout,
    float* __restrict__ save, int n)
{
    int gwarp = (blockIdx.x * blockDim.x + threadIdx.x) >> 5;
    int lane = threadIdx.x & 31;
    if (gwarp >= n) return;
    int node = g_perm[gwarp];

    const float4* U4 = (const float4*)Uin;
    float di = g_dinv[node];
    float4 s4 = U4[(size_t)node * 32 + lane];
    if (save) ((float4*)save)[(size_t)node * 32 + lane] = s4;
    float4 acc = make_float4(s4.x * di, s4.y * di, s4.z * di, s4.w * di);

    int e = g_rowptr[node];
    int end = g_rowptr[node + 1];

    for (; e + 8 <= end; e += 8) {
        int s[8];
        #pragma unroll
        for (int j = 0; j < 8; j++) s[j] = g_col[e + j];
        float w[8];
        #pragma unroll
        for (int j = 0; j < 8; j++) w[j] = g_dinv[s[j]];
        float4 v[8];
        #pragma unroll
        for (int j = 0; j < 8; j++) v[j] = U4[(size_t)s[j] * 32 + lane];
        #pragma unroll
        for (int j = 0; j < 8; j++) {
            acc.x = fmaf(w[j], v[j].x, acc.x);
            acc.y = fmaf(w[j], v[j].y, acc.y);
            acc.z = fmaf(w[j], v[j].z, acc.z);
            acc.w = fmaf(w[j], v[j].w, acc.w);
        }
    }
    for (; e < end; e++) {
        int s = g_col[e];
        float w = g_dinv[s];
        float4 v = U4[(size_t)s * 32 + lane];
        acc.x = fmaf(w, v.x, acc.x);
        acc.y = fmaf(w, v.y, acc.y);
        acc.z = fmaf(w, v.z, acc.z);
        acc.w = fmaf(w, v.w, acc.w);
    }

    ((float4*)Zout)[(size_t)node * 32 + lane] =
        make_float4(di * acc.x, di * acc.y, di * acc.z, di * acc.w);
}

// GEMM body: H = relu(Z @ W + b). 64-row tile, full W in smem, k-paired.
// In-place safe (blocks only read their own 64 rows before storing).
__device__ __forceinline__ void gemm_body(
    const float* __restrict__ Z, const float* __restrict__ W,
    const float* __restrict__ bias, float* __restrict__ H, int n, int blk)
{
    __shared__ float Ws[C * C];
    __shared__ float Zs[64 * C];
    int tid = threadIdx.x;
    int row0 = blk * 64;

    for (int i = tid; i < C * C; i += 256) Ws[i] = W[i];
    for (int i = tid; i < 64 * C; i += 256) {
        int r = row0 + (i >> 7);
        Zs[i] = (r < n) ? Z[(size_t)r * C + (i & 127)] : 0.0f;
    }
    __syncthreads();

    int tn = tid & 31;
    int tm = tid >> 5;
    float acc[8][4];
    #pragma unroll
    for (int r = 0; r < 8; r++)
        #pragma unroll
        for (int c = 0; c < 4; c++) acc[r][c] = 0.0f;

    #pragma unroll 8
    for (int k2 = 0; k2 < C / 2; k2++) {
        float4 wv0 = *(const float4*)&Ws[(2 * k2) * C + tn * 4];
        float4 wv1 = *(const float4*)&Ws[(2 * k2 + 1) * C + tn * 4];
        #pragma unroll
        for (int r = 0; r < 8; r++) {
            float2 z = *(const float2*)&Zs[(tm * 8 + r) * C + 2 * k2];
            acc[r][0] += z.x * wv0.x + z.y * wv1.x;
            acc[r][1] += z.x * wv0.y + z.y * wv1.y;
            acc[r][2] += z.x * wv0.z + z.y * wv1.z;
            acc[r][3] += z.x * wv0.w + z.y * wv1.w;
        }
    }

    float4 bv = ((const float4*)bias)[tn];
    #pragma unroll
    for (int r = 0; r < 8; r++) {
        int row = row0 + tm * 8 + r;
        if (row < n) {
            float4 o;
            o.x = fmaxf(acc[r][0] + bv.x, 0.f);
            o.y = fmaxf(acc[r][1] + bv.y, 0.f);
            o.z = fmaxf(acc[r][2] + bv.z, 0.f);
            o.w = fmaxf(acc[r][3] + bv.w, 0.f);
            *(float4*)&H[(size_t)row * C + tn * 4] = o;
        }
    }
}

// idx 4: gemm1 (writes h1 into xbuf)
__global__ __launch_bounds__(256, 2) void k_gemm(
    const float* __restrict__ Z, const float* __restrict__ W,
    const float* __restrict__ bias, float* __restrict__ H, int n)
{
    gemm_body(Z, W, bias, H, n, blockIdx.x);
}

// idx 6: gemm2 fused with restore (blocks >= gb copy bufB -> xbuf)
__global__ __launch_bounds__(256, 2) void k_gemm_rest(
    const float* __restrict__ Z, const float* __restrict__ W,
    const float* __restrict__ bias, float* __restrict__ H, int n, int gb,
    float* __restrict__ xdst, const float* __restrict__ xsrc, int n4, int rb)
{
    if (blockIdx.x >= gb) {
        int tid = (blockIdx.x - gb) * 256 + threadIdx.x;
        int stride = rb * 256;
        const float4* s4 = (const float4*)xsrc;
        float4* d4 = (float4*)xdst;
        for (int i = tid; i < n4; i += stride) d4[i] = s4[i];
        return;
    }
    gemm_body(Z, W, bias, H, n, blockIdx.x);
}

// idx 7: fused mean-pool + linear head, one block per graph
__global__ __launch_bounds__(256) void k_poolhead(
    const float* __restrict__ H, const float* __restrict__ Wl,
    const float* __restrict__ bl, float* __restrict__ out)
{
    __shared__ float4 sh[8][32];
    __shared__ float pooled[C];
    int g = blockIdx.x;
    int rr = threadIdx.x >> 5;
    int c4 = threadIdx.x & 31;
    int s = g_goff[g], e = g_goff[g + 1];
    const float4* H4 = (const float4*)H;
    float4 acc = make_float4(0.f, 0.f, 0.f, 0.f);
    for (int r = s + rr; r < e; r += 8) {
        float4 v = H4[(size_t)r * 32 + c4];
        acc.x += v.x; acc.y += v.y; acc.z += v.z; acc.w += v.w;
    }
    sh[rr][c4] = acc;
    __syncthreads();
    if (rr == 0) {
        #pragma unroll
        for (int j = 1; j < 8; j++) {
            float4 v = sh[j][c4];
            acc.x += v.x; acc.y += v.y; acc.z += v.z; acc.w += v.w;
        }
        float inv = 1.0f / fmaxf((float)(e - s), 1.0f);
        pooled[c4 * 4 + 0] = acc.x * inv;
        pooled[c4 * 4 + 1] = acc.y * inv;
        pooled[c4 * 4 + 2] = acc.z * inv;
        pooled[c4 * 4 + 3] = acc.w * inv;
    }
    __syncthreads();
    if (threadIdx.x < OC) {
        int o = threadIdx.x;
        float a = bl[o];
        #pragma unroll 4
        for (int k = 0; k < C; k++) a += pooled[k] * Wl[k * OC + o];
        out[g * OC + o] = a;
    }
}

// ---------------- launch (8 nodes) -------------------------------------------
extern "C" void kernel_launch(void* const* d_in, const int* in_sizes, int n_in,
                              void* d_out, int out_size) {
    float*       xbuf = (float*)d_in[0];          // harness buffer; restored each call
    const void*  ei   = d_in[1];
    const void*  bat  = d_in[2];
    const float* W1   = (const float*)d_in[3];
    const float* b1   = (const float*)d_in[4];
    const float* W2   = (const float*)d_in[5];
    const float* b2   = (const float*)d_in[6];
    const float* Wl   = (const float*)d_in[7];
    const float* bl   = (const float*)d_in[8];
    float* out = (float*)d_out;

    int N = in_sizes[0] / C;
    int E = in_sizes[1] / 2;
    int gb = (N + 63) / 64;
    int ab = (N * 32 + 255) / 256;
    int rb = 512;

    k_hist_all <<<1024, 256>>>(ei, bat, E, N);                       // 0
    k_scan     <<<1, 1024>>>(N);                                     // 1
    k_fill     <<<FB + SB, 256>>>(ei, E, N);                         // 2
    // layer 1: weighted gather (degree-sorted order), save x -> bufB
    k_agg      <<<ab, 256>>>(xbuf, g_bufA, g_bufB, N);               // 3  <-- profiled
    // gemm1 writes h1 into xbuf
    k_gemm     <<<gb, 256>>>(g_bufA, W1, b1, xbuf, N);               // 4
    // layer 2: weighted gather (degree-sorted order)
    k_agg      <<<ab, 256>>>(xbuf, g_bufA, nullptr, N);              // 5
    // gemm2 in-place on bufA + restore x from bufB
    k_gemm_rest<<<gb + rb, 256>>>(g_bufA, W2, b2, g_bufA, N, gb,
                                  xbuf, g_bufB, N * 32, rb);         // 6
    k_poolhead <<<NG, 256>>>(g_bufA, Wl, bl, out);                   // 7
}

// round 16
// speedup vs baseline: 1.1051x; 1.0057x over previous
#include <cuda_runtime.h>
#include <math.h>

#define NN 100000
#define NE 1600000
#define C  128
#define OC 64
#define NG 64

// ---------------- static device scratch (zero-initialized .bss) --------------
__device__ float g_bufA[(size_t)NN * C];   // z (agg out) / h2 (gemm2 in-place)
__device__ float g_bufB[(size_t)NN * C];   // saved copy of x during the launch
__device__ int   g_col[NE];
__device__ int   g_cnt[NN];                // zeroed inline by k_scan each replay
__device__ int   g_rowptr[NN + 1];
__device__ int   g_fillptr[NN];
__device__ float g_dinv[NN];
__device__ int   g_gcnt[NG];               // zeroed inline by k_scan each replay
__device__ int   g_goff[NG + 1];

__device__ __forceinline__ int detect64(const int* e32) {
    int is64 = 1;
    #pragma unroll
    for (int i = 0; i < 8; i++) if (e32[2 * i + 1] != 0) is64 = 0;
    return is64;
}

// idx 0: in-degree histogram + per-graph node histogram
__global__ void k_hist_all(const void* ei, const void* bat, int E, int N) {
    int tid = blockIdx.x * blockDim.x + threadIdx.x;
    int stride = gridDim.x * blockDim.x;
    int is64 = detect64((const int*)ei);
    if (is64) {
        const long long* e = (const long long*)ei;
        for (int i = tid; i < E; i += stride)
            atomicAdd(&g_cnt[(int)e[(size_t)E + i]], 1);
        const long long* b = (const long long*)bat;
        for (int i = tid; i < N; i += stride) atomicAdd(&g_gcnt[(int)b[i]], 1);
    } else {
        const int* e = (const int*)ei;
        for (int i = tid; i < E; i += stride)
            atomicAdd(&g_cnt[e[E + i]], 1);
        const int* b = (const int*)bat;
        for (int i = tid; i < N; i += stride) atomicAdd(&g_gcnt[b[i]], 1);
    }
}

// idx 1: single-block fused scan: rowptr/fillptr, dinv, zero cnt, rowptr[N]=E,
// goff from gcnt, zero gcnt.
__global__ void k_scan(int n) {
    __shared__ int wsum[32];
    __shared__ int carry_s;
    int tid = threadIdx.x;
    int lane = tid & 31, wid = tid >> 5;
    if (tid == 0) carry_s = 0;
    __syncthreads();

    for (int base = 0; base < n; base += 1024) {
        int i = base + tid;
        int v = (i < n) ? g_cnt[i] : 0;
        int x = v;
        #pragma unroll
        for (int o = 1; o < 32; o <<= 1) {
            int t = __shfl_up_sync(~0u, x, o);
            if (lane >= o) x += t;
        }
        if (lane == 31) wsum[wid] = x;
        __syncthreads();
        if (wid == 0) {
            int s = wsum[lane];
            #pragma unroll
            for (int o = 1; o < 32; o <<= 1) {
                int t = __shfl_up_sync(~0u, s, o);
                if (lane >= o) s += t;
            }
            wsum[lane] = s;
        }
        __syncthreads();
        int carry = carry_s;
        int warpoff = (wid > 0) ? wsum[wid - 1] : 0;
        int excl = carry + warpoff + x - v;
        if (i < n) {
            g_rowptr[i] = excl;
            g_fillptr[i] = excl;
            g_dinv[i] = rsqrtf((float)(v + 1));
            g_cnt[i] = 0;
        }
        __syncthreads();
        if (tid == 1023) carry_s = carry + wsum[31];
        __syncthreads();
    }
    if (tid == 0) {
        g_rowptr[n] = carry_s;
        int s = 0;
        #pragma unroll
        for (int g = 0; g < NG; g++) {
            g_goff[g] = s;
            s += g_gcnt[g];
            g_gcnt[g] = 0;
        }
        g_goff[NG] = s;
    }
}

// idx 2: CSR column fill (measured 27us)
__global__ void k_fill(const void* ei, int E) {
    int tid = blockIdx.x * blockDim.x + threadIdx.x;
    int stride = gridDim.x * blockDim.x;
    int is64 = detect64((const int*)ei);
    if (is64) {
        const long long* e = (const long long*)ei;
        for (int i = tid; i < E; i += stride) {
            int d = (int)e[(size_t)E + i];
            int s = (int)e[i];
            g_col[atomicAdd(&g_fillptr[d], 1)] = s;
        }
    } else {
        const int* e = (const int*)ei;
        for (int i = tid; i < E; i += stride) {
            int d = e[E + i];
            int s = e[i];
            g_col[atomicAdd(&g_fillptr[d], 1)] = s;
        }
    }
}

// idx 3 (PROFILED) / 4 / 6 / 7: channel-split aggregation (R5-measured 176us/pass).
// One launch covers 64 channels (pass 0: ch 0-63, pass 1: ch 64-127), so the
// per-pass gather working set (25.6 MB) is L2-resident.
// Each warp = 2 nodes (16-lane sub-warps x float4 = 64 ch per node).
// z_i = di*(di*u_i + sum_j dj*u_j); save != nullptr backs up self rows.
__global__ __launch_bounds__(256) void k_agg64(
    const float* __restrict__ Uin, float* __restrict__ Zout,
    float* __restrict__ save, int n, int pass)
{
    int gwarp = (blockIdx.x * blockDim.x + threadIdx.x) >> 5;
    int lane = threadIdx.x & 31;
    int half = lane >> 4;
    int hl   = lane & 15;
    int node = gwarp * 2 + half;
    if (node >= n) return;

    const float4* U4 = (const float4*)Uin;
    int poff = pass * 16;
    size_t rowbase = (size_t)node * 32 + poff + hl;

    float di = g_dinv[node];
    float4 s4 = U4[rowbase];
    if (save) ((float4*)save)[rowbase] = s4;
    float4 acc = make_float4(s4.x * di, s4.y * di, s4.z * di, s4.w * di);

    int e = g_rowptr[node];
    int end = g_rowptr[node + 1];

    for (; e + 8 <= end; e += 8) {
        int s[8];
        #pragma unroll
        for (int j = 0; j < 8; j++) s[j] = g_col[e + j];
        float w[8];
        #pragma unroll
        for (int j = 0; j < 8; j++) w[j] = g_dinv[s[j]];
        float4 v[8];
        #pragma unroll
        for (int j = 0; j < 8; j++) v[j] = U4[(size_t)s[j] * 32 + poff + hl];
        #pragma unroll
        for (int j = 0; j < 8; j++) {
            acc.x = fmaf(w[j], v[j].x, acc.x);
            acc.y = fmaf(w[j], v[j].y, acc.y);
            acc.z = fmaf(w[j], v[j].z, acc.z);
            acc.w = fmaf(w[j], v[j].w, acc.w);
        }
    }
    for (; e < end; e++) {
        int s = g_col[e];
        float w = g_dinv[s];
        float4 v = U4[(size_t)s * 32 + poff + hl];
        acc.x = fmaf(w, v.x, acc.x);
        acc.y = fmaf(w, v.y, acc.y);
        acc.z = fmaf(w, v.z, acc.z);
        acc.w = fmaf(w, v.w, acc.w);
    }

    ((float4*)Zout)[rowbase] =
        make_float4(di * acc.x, di * acc.y, di * acc.z, di * acc.w);
}

// GEMM body: H = relu(Z @ W + b). 64-row tile, full W in smem, k-paired.
// In-place safe (blocks only read their own 64 rows before storing).
__device__ __forceinline__ void gemm_body(
    const float* __restrict__ Z, const float* __restrict__ W,
    const float* __restrict__ bias, float* __restrict__ H, int n, int blk)
{
    __shared__ float Ws[C * C];
    __shared__ float Zs[64 * C];
    int tid = threadIdx.x;
    int row0 = blk * 64;

    for (int i = tid; i < C * C; i += 256) Ws[i] = W[i];
    for (int i = tid; i < 64 * C; i += 256) {
        int r = row0 + (i >> 7);
        Zs[i] = (r < n) ? Z[(size_t)r * C + (i & 127)] : 0.0f;
    }
    __syncthreads();

    int tn = tid & 31;
    int tm = tid >> 5;
    float acc[8][4];
    #pragma unroll
    for (int r = 0; r < 8; r++)
        #pragma unroll
        for (int c = 0; c < 4; c++) acc[r][c] = 0.0f;

    #pragma unroll 8
    for (int k2 = 0; k2 < C / 2; k2++) {
        float4 wv0 = *(const float4*)&Ws[(2 * k2) * C + tn * 4];
        float4 wv1 = *(const float4*)&Ws[(2 * k2 + 1) * C + tn * 4];
        #pragma unroll
        for (int r = 0; r < 8; r++) {
            float2 z = *(const float2*)&Zs[(tm * 8 + r) * C + 2 * k2];
            acc[r][0] += z.x * wv0.x + z.y * wv1.x;
            acc[r][1] += z.x * wv0.y + z.y * wv1.y;
            acc[r][2] += z.x * wv0.z + z.y * wv1.z;
            acc[r][3] += z.x * wv0.w + z.y * wv1.w;
        }
    }

    float4 bv = ((const float4*)bias)[tn];
    #pragma unroll
    for (int r = 0; r < 8; r++) {
        int row = row0 + tm * 8 + r;
        if (row < n) {
            float4 o;
            o.x = fmaxf(acc[r][0] + bv.x, 0.f);
            o.y = fmaxf(acc[r][1] + bv.y, 0.f);
            o.z = fmaxf(acc[r][2] + bv.z, 0.f);
            o.w = fmaxf(acc[r][3] + bv.w, 0.f);
            *(float4*)&H[(size_t)row * C + tn * 4] = o;
        }
    }
}

// idx 5: gemm1 (writes h1 into xbuf)
__global__ __launch_bounds__(256, 2) void k_gemm(
    const float* __restrict__ Z, const float* __restrict__ W,
    const float* __restrict__ bias, float* __restrict__ H, int n)
{
    gemm_body(Z, W, bias, H, n, blockIdx.x);
}

// idx 8: gemm2 fused with restore (blocks >= gb copy bufB -> xbuf)
__global__ __launch_bounds__(256, 2) void k_gemm_rest(
    const float* __restrict__ Z, const float* __restrict__ W,
    const float* __restrict__ bias, float* __restrict__ H, int n, int gb,
    float* __restrict__ xdst, const float* __restrict__ xsrc, int n4, int rb)
{
    if (blockIdx.x >= gb) {
        int tid = (blockIdx.x - gb) * 256 + threadIdx.x;
        int stride = rb * 256;
        const float4* s4 = (const float4*)xsrc;
        float4* d4 = (float4*)xdst;
        for (int i = tid; i < n4; i += stride) d4[i] = s4[i];
        return;
    }
    gemm_body(Z, W, bias, H, n, blockIdx.x);
}

// idx 9: fused mean-pool + linear head, one block per graph
__global__ __launch_bounds__(256) void k_poolhead(
    const float* __restrict__ H, const float* __restrict__ Wl,
    const float* __restrict__ bl, float* __restrict__ out)
{
    __shared__ float4 sh[8][32];
    __shared__ float pooled[C];
    int g = blockIdx.x;
    int rr = threadIdx.x >> 5;
    int c4 = threadIdx.x & 31;
    int s = g_goff[g], e = g_goff[g + 1];
    const float4* H4 = (const float4*)H;
    float4 acc = make_float4(0.f, 0.f, 0.f, 0.f);
    for (int r = s + rr; r < e; r += 8) {
        float4 v = H4[(size_t)r * 32 + c4];
        acc.x += v.x; acc.y += v.y; acc.z += v.z; acc.w += v.w;
    }
    sh[rr][c4] = acc;
    __syncthreads();
    if (rr == 0) {
        #pragma unroll
        for (int j = 1; j < 8; j++) {
            float4 v = sh[j][c4];
            acc.x += v.x; acc.y += v.y; acc.z += v.z; acc.w += v.w;
        }
        float inv = 1.0f / fmaxf((float)(e - s), 1.0f);
        pooled[c4 * 4 + 0] = acc.x * inv;
        pooled[c4 * 4 + 1] = acc.y * inv;
        pooled[c4 * 4 + 2] = acc.z * inv;
        pooled[c4 * 4 + 3] = acc.w * inv;
    }
    __syncthreads();
    if (threadIdx.x < OC) {
        int o = threadIdx.x;
        float a = bl[o];
        #pragma unroll 4
        for (int k = 0; k < C; k++) a += pooled[k] * Wl[k * OC + o];
        out[g * OC + o] = a;
    }
}

// ---------------- launch (10 nodes) ------------------------------------------
extern "C" void kernel_launch(void* const* d_in, const int* in_sizes, int n_in,
                              void* d_out, int out_size) {
    float*       xbuf = (float*)d_in[0];          // harness buffer; restored each call
    const void*  ei   = d_in[1];
    const void*  bat  = d_in[2];
    const float* W1   = (const float*)d_in[3];
    const float* b1   = (const float*)d_in[4];
    const float* W2   = (const float*)d_in[5];
    const float* b2   = (const float*)d_in[6];
    const float* Wl   = (const float*)d_in[7];
    const float* bl   = (const float*)d_in[8];
    float* out = (float*)d_out;

    int N = in_sizes[0] / C;
    int E = in_sizes[1] / 2;
    int gb = (N + 63) / 64;
    int ab = (N * 16 + 255) / 256;    // agg blocks per 64-ch pass (2 nodes/warp)
    int rb = 512;

    k_hist_all <<<1024, 256>>>(ei, bat, E, N);                       // 0
    k_scan     <<<1, 1024>>>(N);                                     // 1
    k_fill     <<<1024, 256>>>(ei, E);                               // 2
    // layer 1: channel-split weighted gather from xbuf, save x -> bufB
    k_agg64    <<<ab, 256>>>(xbuf, g_bufA, g_bufB, N, 0);            // 3  <-- profiled
    k_agg64    <<<ab, 256>>>(xbuf, g_bufA, g_bufB, N, 1);            // 4
    // gemm1 writes h1 into xbuf
    k_gemm     <<<gb, 256>>>(g_bufA, W1, b1, xbuf, N);               // 5
    // layer 2: channel-split weighted gather from xbuf
    k_agg64    <<<ab, 256>>>(xbuf, g_bufA, nullptr, N, 0);           // 6
    k_agg64    <<<ab, 256>>>(xbuf, g_bufA, nullptr, N, 1);           // 7
    // gemm2 in-place on bufA + restore x from bufB
    k_gemm_rest<<<gb + rb, 256>>>(g_bufA, W2, b2, g_bufA, N, gb,
                                  xbuf, g_bufB, N * 32, rb);         // 8
    k_poolhead <<<NG, 256>>>(g_bufA, Wl, bl, out);                   // 9
}